// round 17
// baseline (speedup 1.0000x reference)
#include <cuda_runtime.h>
#include <cuda_bf16.h>

// ---------------- problem constants ----------------
#define BB   4
#define TT   16
#define NN   1000
#define FIN  8
#define EE   8000
#define EP   9000          // edges + self loops
#define HID  64
#define HEADS 4
#define LL   5
#define GG   64            // B*T graphs
#define RR   64000         // G*N rows
#define NH   64000         // N*HID
#define GATES 192
#define KCH  512
#define NCHUNK 125

// H layout: slice-major. Column c of row r lives at
//   H[(c>>4) * (RR*16) + r*16 + (c&15)]
#define HSLICE (RR * 16)

// agg7 smem layout (floats):
//   Hs0[16000] | pad 16 | Hs1[16000] | srec[9000 float2] | sls[1000] | sld[1000] | soff[1001]
#define AGG7_PAD    16
#define AGG7_HALF   (NN * 16)
#define AGG7_SREC   (2 * AGG7_HALF + AGG7_PAD)            // 32016 (8B aligned)
#define AGG7_SLS    (AGG7_SREC + 2 * EP)                  // 50016
#define AGG7_SLD    (AGG7_SLS + NN)                       // 51016
#define AGG7_SOFF   (AGG7_SLD + NN)                       // 52016
#define AGG7_SMEM   ((AGG7_SOFF + NN + 1) * 4)            // 212068 B

// ---- Blackwell packed fp32x2 FMA (2 IEEE fp32 FMAs per instruction) ----
#define FMA_F32X2(d, a, b, c) \
    asm("fma.rn.f32x2 %0, %1, %2, %3;" : "=l"(d) : "l"(a), "l"(b), "l"(c))
#define PACK_F32X2(out, lo, hi) \
    asm("mov.b64 %0, {%1, %2};" : "=l"(out) : "f"(lo), "f"(hi))
#define UNPACK_F32X2(lo, hi, in) \
    asm("mov.b64 {%0, %1}, %2;" : "=f"(lo), "=f"(hi) : "l"(in))

// ---------------- device scratch ----------------
__device__ float g_X0[RR * HID];
__device__ float g_X1[RR * HID];
__device__ float g_Ha[16 * HSLICE];          // H ping
__device__ float g_Hb[16 * HSLICE];          // H pong
__device__ float g_ls[RR * HEADS];
__device__ float g_ld[RR * HEADS];
__device__ int   g_off[NN + 1];
__device__ int   g_srcList[EP];
__device__ int   g_eid[EP];
__device__ float g_GIpart[NCHUNK * GG * GATES];
__device__ float g_GI[GG * GATES];
__device__ float g_hT[BB * HID];

// ---------------- CSR build: ONE kernel, one block (deterministic) -----------
__global__ void __launch_bounds__(1024) k_csr_all(const int* __restrict__ edge_index) {
    __shared__ int scnt[1024];
    __shared__ int sscan[1024];
    __shared__ int scur[1024];
    int tid = threadIdx.x;
    scnt[tid] = 0;
    __syncthreads();
    for (int e = tid; e < EE; e += 1024)
        atomicAdd(&scnt[edge_index[EE + e]], 1);
    __syncthreads();
    int v = (tid < NN) ? (scnt[tid] + 1) : 0;    // +1 self loop
    sscan[tid] = v;
    __syncthreads();
    for (int o = 1; o < 1024; o <<= 1) {
        int add = (tid >= o) ? sscan[tid - o] : 0;
        __syncthreads();
        sscan[tid] += add;
        __syncthreads();
    }
    if (tid < NN) {
        g_off[tid + 1] = sscan[tid];
        scur[tid] = (tid == 0) ? 0 : sscan[tid - 1];
    }
    if (tid == 0) g_off[0] = 0;
    __syncthreads();
    for (int e = tid; e < EP; e += 1024) {
        int s, d;
        if (e < EE) { s = edge_index[e]; d = edge_index[EE + e]; }
        else        { s = e - EE;        d = e - EE; }
        int pos = atomicAdd(&scur[d], 1);
        g_srcList[pos] = s;
        g_eid[pos] = e;
    }
    __syncthreads();
    if (tid < NN) {                       // stable order by edge id
        int s0 = g_off[tid], s1 = g_off[tid + 1];
        for (int i = s0 + 1; i < s1; i++) {
            int id = g_eid[i], sv = g_srcList[i];
            int j = i - 1;
            while (j >= s0 && g_eid[j] > id) {
                g_eid[j + 1] = g_eid[j];
                g_srcList[j + 1] = g_srcList[j];
                j--;
            }
            g_eid[j + 1] = id;
            g_srcList[j + 1] = sv;
        }
    }
}

// ---------------- input projection (half grid per launch) ----------------
__global__ void k_input_fc(const float* __restrict__ x,
                           const float* __restrict__ W_in,
                           const float* __restrict__ b_in, int rowBase) {
    int tid = threadIdx.x;
    int r = rowBase + blockIdx.x * 4 + (tid >> 6);
    int c = tid & 63;
    float s = b_in[c];
#pragma unroll
    for (int f = 0; f < FIN; f++)
        s += x[r * FIN + f] * W_in[f * HID + c];
    g_X0[r * HID + c] = s;
}

// ---------------- GAT GEMM v3: 64x128 tile, f32x2, H ping-pong ---------------
// grid (1000, 2): rowBase = bx*64, colHalf = by (heads 2*by, 2*by+1).
// bgPrev == nullptr: As from g_X0 (layer 0); else fused finish from Hin.
// hSel: bit0 = out buffer (0=Ha,1=Hb), bit1 = in buffer.
__global__ void __launch_bounds__(256, 3) k_gat_gemm(const float* __restrict__ bgPrev,
                                                     const float* __restrict__ W,
                                                     const float* __restrict__ asrc,
                                                     const float* __restrict__ adst,
                                                     int hSel) {
    __shared__ float sm[8192];                  // 32KB, aliased
    float (*As)[64]  = (float(*)[64])sm;        // [64][64]
    float (*Ws)[128] = (float(*)[128])(sm + 4096); // [32][128]
    float* __restrict__ Hout = (hSel & 1) ? g_Hb : g_Ha;
    const float* __restrict__ Hin = (hSel & 2) ? g_Hb : g_Ha;
    int rowBase = blockIdx.x * 64;
    int colHalf = blockIdx.y;                   // 0 or 1
    int colBase4 = colHalf * 32;                // float4 units within 256-col row
    int tid = threadIdx.x;

    if (bgPrev == nullptr) {
        const float4* X4 = (const float4*)(g_X0 + (size_t)rowBase * 64);
#pragma unroll
        for (int q = 0; q < 4; q++) {
            int idx = tid + q * 256;
            int r = idx & 63, k4 = idx >> 6;
            float4 v = X4[r * 16 + k4];
            As[k4 * 4 + 0][r] = v.x;
            As[k4 * 4 + 1][r] = v.y;
            As[k4 * 4 + 2][r] = v.z;
            As[k4 * 4 + 3][r] = v.w;
        }
    } else {
#pragma unroll
        for (int q = 0; q < 4; q++) {
            int idx = tid + q * 256;
            int r = idx & 63, c = (idx >> 6) * 4;    // c in {0,4,...,60}
            size_t rg = (size_t)(rowBase + r) * 16 + (c & 15);
            float4 v = make_float4(0.f, 0.f, 0.f, 0.f);
#pragma unroll
            for (int h = 0; h < HEADS; h++) {
                float4 t = *(const float4*)&Hin[(size_t)(h * 4 + (c >> 4)) * HSLICE + rg];
                v.x += t.x; v.y += t.y; v.z += t.z; v.w += t.w;
            }
            float e0 = 0.25f * v.x + bgPrev[c];
            float e1 = 0.25f * v.y + bgPrev[c + 1];
            float e2 = 0.25f * v.z + bgPrev[c + 2];
            float e3 = 0.25f * v.w + bgPrev[c + 3];
            As[c + 0][r] = e0 > 0.f ? e0 : expm1f(e0);
            As[c + 1][r] = e1 > 0.f ? e1 : expm1f(e1);
            As[c + 2][r] = e2 > 0.f ? e2 : expm1f(e2);
            As[c + 3][r] = e3 > 0.f ? e3 : expm1f(e3);
        }
    }

    int lane = tid & 31, w = tid >> 5;
    int ry2 = lane >> 2, cx2 = lane & 3;
    int cg = w * 4 + cx2;                       // 0..31 (4-col group within 128)
    unsigned long long accP[4][4];              // [row pair][col]
#pragma unroll
    for (int pi = 0; pi < 4; pi++)
#pragma unroll
        for (int j = 0; j < 4; j++) accP[pi][j] = 0ull;
    const float4* W4 = (const float4*)W;

#pragma unroll
    for (int half = 0; half < 2; half++) {
        __syncthreads();
#pragma unroll
        for (int q = 0; q < 4; q++) {
            int idx = tid + q * 256;            // 0..1023
            int kk = idx >> 5, c4 = idx & 31;
            ((float4*)Ws)[idx] = W4[(half * 32 + kk) * 64 + colBase4 + c4];
        }
        __syncthreads();
#pragma unroll
        for (int kk = 0; kk < 32; kk++) {
            int k = half * 32 + kk;
            ulonglong2 aLo = *(const ulonglong2*)&As[k][ry2 * 4];
            ulonglong2 aHi = *(const ulonglong2*)&As[k][32 + ry2 * 4];
            unsigned long long aP[4] = {aLo.x, aLo.y, aHi.x, aHi.y};
            float4 b = *(const float4*)&Ws[kk][cg * 4];
            float bv[4] = {b.x, b.y, b.z, b.w};
            unsigned long long bD[4];
#pragma unroll
            for (int j = 0; j < 4; j++) PACK_F32X2(bD[j], bv[j], bv[j]);
#pragma unroll
            for (int pi = 0; pi < 4; pi++)
#pragma unroll
                for (int j = 0; j < 4; j++)
                    FMA_F32X2(accP[pi][j], aP[pi], bD[j], accP[pi][j]);
        }
    }
    // unpack: row pair pi covers acc rows 2*pi, 2*pi+1
    float acc[8][4];
#pragma unroll
    for (int pi = 0; pi < 4; pi++)
#pragma unroll
        for (int j = 0; j < 4; j++)
            UNPACK_F32X2(acc[pi * 2][j], acc[pi * 2 + 1][j], accP[pi][j]);

    // store H tile to Hout, slice-major (one float4 per row)
    {
        int sl = colHalf * 8 + (cg >> 2);
        int chB = (cg & 3) * 4;
#pragma unroll
        for (int ii = 0; ii < 8; ii++) {
            int r = rowBase + ((ii < 4) ? (ry2 * 4 + ii) : (32 + ry2 * 4 + (ii - 4)));
            *(float4*)&Hout[(size_t)sl * HSLICE + r * 16 + chB] =
                make_float4(acc[ii][0], acc[ii][1], acc[ii][2], acc[ii][3]);
        }
    }

    // ---- fused ls/ld epilogue (2 heads per block) ----
    __syncthreads();                            // done reading As/Ws
    float (*redls)[2][16] = (float(*)[2][16])sm;          // [64][2][16] = 8KB
    float (*redld)[2][16] = (float(*)[2][16])(sm + 2048);
    float as_v[4], ad_v[4];
#pragma unroll
    for (int j = 0; j < 4; j++) {
        as_v[j] = asrc[colHalf * 128 + cg * 4 + j];
        ad_v[j] = adst[colHalf * 128 + cg * 4 + j];
    }
    int hA = cg >> 4;                           // local head (0/1)
    int slot = (w & 3) * 4 + cx2;               // 0..15
#pragma unroll
    for (int ii = 0; ii < 8; ii++) {
        int r = (ii < 4) ? (ry2 * 4 + ii) : (32 + ry2 * 4 + (ii - 4));
        float pls = 0, pld = 0;
#pragma unroll
        for (int j = 0; j < 4; j++) {
            pls += acc[ii][j] * as_v[j];
            pld += acc[ii][j] * ad_v[j];
        }
        redls[r][hA][slot] = pls;
        redld[r][hA][slot] = pld;
    }
    __syncthreads();
    if (tid < 128) {
        int r = tid >> 1, hh = tid & 1;
        float s = 0, d = 0;
#pragma unroll
        for (int k = 0; k < 16; k++) { s += redls[r][hh][k]; d += redld[r][hh][k]; }
        g_ls[(rowBase + r) * 4 + colHalf * 2 + hh] = s;
        g_ld[(rowBase + r) * 4 + colHalf * 2 + hh] = d;
    }
}

// ---------------- GAT aggregate v7: float2 records, in-place on H buffer -----
// grid (GG, 8): sl2 covers slices {sl2*2, sl2*2+1}; head h = sl2>>1.
__global__ void __launch_bounds__(1024) k_gat_agg7(int hOut) {
    extern __shared__ float sm7[];
    float*  Hs   = sm7;
    float2* srec = (float2*)(sm7 + AGG7_SREC);
    float*  sls  = sm7 + AGG7_SLS;
    float*  sld  = sm7 + AGG7_SLD;
    int*    soff = (int*)(sm7 + AGG7_SOFF);

    float* __restrict__ Hbuf = hOut ? g_Hb : g_Ha;
    int g = blockIdx.x, sl2 = blockIdx.y;
    int sl0 = sl2 * 2;
    int h = sl2 >> 1;
    int tid = threadIdx.x;
    int lane = tid & 31, w = tid >> 5;
    size_t gb = (size_t)g * NN;
    float* __restrict__ H0 = Hbuf + (size_t)sl0 * HSLICE + gb * 16;
    float* __restrict__ H1 = Hbuf + (size_t)(sl0 + 1) * HSLICE + gb * 16;

    // Phase A: stage H slices, edge records (src only), per-head ls/ld, g_off
    {
        const float4* s0 = (const float4*)H0;
        const float4* s1 = (const float4*)H1;
        float4* d0 = (float4*)Hs;
        float4* d1 = (float4*)(Hs + AGG7_HALF + AGG7_PAD);
        for (int idx = tid; idx < NN * 4; idx += 1024) {
            d0[idx] = s0[idx];
            d1[idx] = s1[idx];
        }
        for (int j = tid; j < EP; j += 1024)
            srec[j].y = __int_as_float(g_srcList[j] * 16);
        const float4* ls4 = (const float4*)(g_ls + gb * HEADS);
        const float4* ld4 = (const float4*)(g_ld + gb * HEADS);
        for (int n = tid; n < NN; n += 1024) {
            float4 a = ls4[n];
            float4 b = ld4[n];
            sls[n] = ((const float*)&a)[h];
            sld[n] = ((const float*)&b)[h];
        }
        for (int n = tid; n < NN + 1; n += 1024)
            soff[n] = g_off[n];
    }
    __syncthreads();

    // Phase W: thread-per-node normalized softmax weights into srec.x
    for (int n = tid; n < NN; n += 1024) {
        int s0 = soff[n], s1 = soff[n + 1];
        float ldv = sld[n];
        float sum = 0.f;
        for (int j = s0; j < s1; j++) {
            int s = __float_as_int(srec[j].y) >> 4;
            float v = sls[s] + ldv;
            v = v > 0.f ? v : 0.2f * v;
            float wv = __expf(v);
            srec[j].x = wv;
            sum += wv;
        }
        float inv = 1.f / (sum + 1e-16f);
        for (int j = s0; j < s1; j++)
            srec[j].x *= inv;
    }
    __syncthreads();

    int eh  = lane >> 4;                        // edge parity half
    int ch2 = lane & 15;                        // channel-pair index
    int chOff2 = (ch2 >> 3) * (AGG7_HALF + AGG7_PAD) + (ch2 & 7) * 2;
    float* __restrict__ Hout = ((ch2 < 8) ? H0 : H1) + (ch2 & 7) * 2;

    // Phase B: warp per node; each lane = (edge parity, channel pair)
    for (int n = w; n < NN; n += 32) {
        int s0 = soff[n], s1 = soff[n + 1];
        float ax = 0.f, ay = 0.f;
        int j = s0 + eh;
        for (; j + 2 < s1; j += 4) {
            float2 r0 = srec[j];
            float2 r1 = srec[j + 2];
            const float2 h0 = *(const float2*)&Hs[__float_as_int(r0.y) + chOff2];
            const float2 h1 = *(const float2*)&Hs[__float_as_int(r1.y) + chOff2];
            ax += r0.x * h0.x + r1.x * h1.x;
            ay += r0.x * h0.y + r1.x * h1.y;
        }
        if (j < s1) {
            float2 r0 = srec[j];
            const float2 h0 = *(const float2*)&Hs[__float_as_int(r0.y) + chOff2];
            ax += r0.x * h0.x;
            ay += r0.x * h0.y;
        }
        ax += __shfl_down_sync(0xffffffffu, ax, 16);
        ay += __shfl_down_sync(0xffffffffu, ay, 16);
        if (eh == 0)
            *(float2*)&Hout[n * 16] = make_float2(ax, ay);   // in-place
    }
}

// ---------------- head mean + bias + elu -> X1 (final layer only) ------------
__global__ void k_finish(const float* __restrict__ bg_l, int hOut) {
    const float* __restrict__ Hbuf = hOut ? g_Hb : g_Ha;
    int tid = threadIdx.x;
    int r = blockIdx.x * 4 + (tid >> 6);
    int c = tid & 63;
    float v = 0.f;
#pragma unroll
    for (int h = 0; h < HEADS; h++) {
        int cc = h * 64 + c;
        v += Hbuf[(size_t)(cc >> 4) * HSLICE + (size_t)r * 16 + (cc & 15)];
    }
    v = 0.25f * v + bg_l[c];
    v = v > 0.f ? v : expm1f(v);
    g_X1[(size_t)r * 64 + c] = v;
}

// ---------------- GI split-K GEMM -------------------------------------------
__global__ void __launch_bounds__(256) k_gi_gemm(const float* __restrict__ Wih) {
    __shared__ float As[64][33];
    __shared__ float Ws[64][33];
    int kBase = blockIdx.x * KCH;
    int gateBase = blockIdx.y * 64;
    int tid = threadIdx.x;
    int tx = tid & 15, ty = tid >> 4;
    float acc[4][4] = {};
    for (int kt = 0; kt < KCH / 32; kt++) {
        int k0 = kBase + kt * 32;
#pragma unroll
        for (int i = 0; i < 8; i++) {
            int idx = tid + i * 256;
            int r = idx >> 5, kk = idx & 31;
            As[r][kk] = g_X1[r * NH + k0 + kk];
            Ws[r][kk] = Wih[(size_t)(gateBase + r) * NH + k0 + kk];
        }
        __syncthreads();
#pragma unroll
        for (int kk = 0; kk < 32; kk++) {
            float a[4], wv[4];
#pragma unroll
            for (int i = 0; i < 4; i++) a[i] = As[ty * 4 + i][kk];
#pragma unroll
            for (int j = 0; j < 4; j++) wv[j] = Ws[tx * 4 + j][kk];
#pragma unroll
            for (int i = 0; i < 4; i++)
#pragma unroll
                for (int j = 0; j < 4; j++)
                    acc[i][j] += a[i] * wv[j];
        }
        __syncthreads();
    }
#pragma unroll
    for (int i = 0; i < 4; i++)
#pragma unroll
        for (int j = 0; j < 4; j++)
            g_GIpart[(blockIdx.x * GG + ty * 4 + i) * GATES + gateBase + tx * 4 + j] = acc[i][j];
}

__global__ void k_gi_reduce(const float* __restrict__ b_ih) {
    int idx = blockIdx.x * blockDim.x + threadIdx.x;
    int j = idx % GATES;
    float s = b_ih[j];
    for (int kc = 0; kc < NCHUNK; kc++)
        s += g_GIpart[kc * GG * GATES + idx];
    g_GI[idx] = s;
}

// ---------------- GRU recurrence ----------------
__global__ void __launch_bounds__(256) k_gru(const float* __restrict__ Whh,
                                             const float* __restrict__ bhh) {
    __shared__ float h[BB][HID];
    __shared__ float gh[BB][GATES];
    int tid = threadIdx.x;
    h[tid >> 6][tid & 63] = 0.f;
    __syncthreads();
    for (int t = 0; t < TT; t++) {
#pragma unroll
        for (int q = 0; q < 3; q++) {
            int idx = tid + q * 256;
            int b = idx / GATES, j = idx % GATES;
            float s = bhh[j];
#pragma unroll
            for (int c = 0; c < HID; c++)
                s += h[b][c] * Whh[j * HID + c];
            gh[b][j] = s;
        }
        __syncthreads();
        int b = tid >> 6, c = tid & 63;
        int g = b * TT + t;
        float ir = g_GI[g * GATES + c]        + gh[b][c];
        float iz = g_GI[g * GATES + 64 + c]   + gh[b][64 + c];
        float in = g_GI[g * GATES + 128 + c];
        float hn = gh[b][128 + c];
        float r = 1.f / (1.f + expf(-ir));
        float z = 1.f / (1.f + expf(-iz));
        float nn = tanhf(in + r * hn);
        float hnew = (1.f - z) * nn + z * h[b][c];
        __syncthreads();
        h[b][c] = hnew;
        __syncthreads();
    }
    g_hT[tid] = h[tid >> 6][tid & 63];
}

// ---------------- final FC ----------------
__global__ void k_fc(const float* __restrict__ Wfc, const float* __restrict__ bfc,
                     float* __restrict__ out) {
    int b = blockIdx.x;
    int n = blockIdx.y * 256 + threadIdx.x;
    if (n >= NN) return;
    float s = bfc[n];
#pragma unroll
    for (int c = 0; c < HID; c++)
        s += g_hT[b * HID + c] * Wfc[c * NN + n];
    out[b * NN + n] = s;
}

// ---------------- launcher ----------------
extern "C" void kernel_launch(void* const* d_in, const int* in_sizes, int n_in,
                              void* d_out, int out_size) {
    const float* x_seq = (const float*)d_in[0];
    const int*   edge_index = (const int*)d_in[1];
    const float* W_in = (const float*)d_in[3];
    const float* b_in = (const float*)d_in[4];
    const float* Wg   = (const float*)d_in[5];
    const float* a_src= (const float*)d_in[6];
    const float* a_dst= (const float*)d_in[7];
    const float* bg   = (const float*)d_in[8];
    const float* W_ih = (const float*)d_in[9];
    const float* W_hh = (const float*)d_in[10];
    const float* b_ih = (const float*)d_in[11];
    const float* b_hh = (const float*)d_in[12];
    const float* W_fc = (const float*)d_in[13];
    const float* b_fc = (const float*)d_in[14];
    float* out = (float*)d_out;

    cudaFuncSetAttribute(k_gat_agg7,
                         cudaFuncAttributeMaxDynamicSharedMemorySize, AGG7_SMEM);

    // launches 1-3; #4 = layer-0 gemm (ncu slot)
    k_csr_all<<<1, 1024>>>(edge_index);
    k_input_fc<<<RR / 8, 256>>>(x_seq, W_in, b_in, 0);
    k_input_fc<<<RR / 8, 256>>>(x_seq, W_in, b_in, RR / 2);

    for (int l = 0; l < LL; l++) {
        const float* bgPrev = (l == 0) ? nullptr : (bg + (size_t)(l - 1) * HID);
        int outB = l & 1;                    // layer l writes Ha if even, Hb if odd
        int inB  = 1 - outB;                 // reads the other (valid for l>=1)
        int hSel = outB | (inB << 1);
        k_gat_gemm<<<dim3(RR / 64, 2), 256>>>(bgPrev, Wg + (size_t)l * HID * 256,
                                              a_src + (size_t)l * HEADS * HID,
                                              a_dst + (size_t)l * HEADS * HID,
                                              hSel);
        k_gat_agg7<<<dim3(GG, 8), 1024, AGG7_SMEM>>>(outB);
    }
    // layer 4 (even) wrote g_Ha -> finish reads hOut=0
    k_finish<<<RR / 4, 256>>>(bg + (size_t)(LL - 1) * HID, 0);

    k_gi_gemm<<<dim3(NCHUNK, 3), 256>>>(W_ih);
    k_gi_reduce<<<(GG * GATES) / 256, 256>>>(b_ih);
    k_gru<<<1, 256>>>(W_hh, b_hh);
    k_fc<<<dim3(BB, 4), 256>>>(W_fc, b_fc, out);
}